// round 2
// baseline (speedup 1.0000x reference)
#include <cuda_runtime.h>
#include <stdint.h>

#define NUM_BINS   256
#define GRID       152              // GB300: 152 SMs, 1 resident block each
#define NWARPS     7
#define NTHREADS   (NWARPS * 32)    // 224
#define HIST_F32_PER_WARP (NUM_BINS * 32)           // 8192 floats = 32 KB
#define SMEM_FLOATS (NWARPS * HIST_F32_PER_WARP)    // 57344
#define SMEM_BYTES  (SMEM_FLOATS * 4)               // 229376 <= 232448 limit

#define BIAS 1024.0f
#define INV_BIAS (1.0f / 1024.0f)

// per-block partial results (no allocation allowed -> __device__ globals)
__device__ float g_psum[GRID * NUM_BINS];
__device__ float g_pcnt[GRID * NUM_BINS];

__device__ __forceinline__ void rmw1(float* hb, int bin, float v) {
    // hb already offset by (warp, lane); column layout: entry = hb + bin*32
    float* p = hb + ((bin & 255) << 5);
    *p = *p + (v + BIAS);   // cell accumulates cnt*1024 + sum(x)
}

__device__ __forceinline__ void rmw4(float* hb, float4 xv, int4 iv) {
    rmw1(hb, iv.x, xv.x);
    rmw1(hb, iv.y, xv.y);
    rmw1(hb, iv.z, xv.z);
    rmw1(hb, iv.w, xv.w);
}

__global__ __launch_bounds__(NTHREADS, 1)
void seg_hist_kernel(const float* __restrict__ x,
                     const int*   __restrict__ idx,
                     int E)
{
    extern __shared__ float smem[];
    const int tid  = threadIdx.x;
    const int lane = tid & 31;
    const int warp = tid >> 5;

    float* hb = smem + warp * HIST_F32_PER_WARP + lane;

    // zero the private histograms
    #pragma unroll 4
    for (int i = tid; i < SMEM_FLOATS; i += NTHREADS)
        smem[i] = 0.0f;
    __syncthreads();

    const float4* __restrict__ x4 = (const float4*)x;
    const int4*   __restrict__ i4 = (const int4*)idx;
    const int G = E >> 2;                       // float4 groups
    const int stride = GRID * NTHREADS;         // 34048

    int g = blockIdx.x * NTHREADS + tid;

    // main loop: 4 prefetched groups (16 elements) per iteration
    for (; g + 3 * stride < G; g += 4 * stride) {
        float4 a0 = x4[g];
        float4 a1 = x4[g + stride];
        float4 a2 = x4[g + 2 * stride];
        float4 a3 = x4[g + 3 * stride];
        int4   b0 = i4[g];
        int4   b1 = i4[g + stride];
        int4   b2 = i4[g + 2 * stride];
        int4   b3 = i4[g + 3 * stride];
        rmw4(hb, a0, b0);
        rmw4(hb, a1, b1);
        rmw4(hb, a2, b2);
        rmw4(hb, a3, b3);
    }
    // tail
    for (; g < G; g += stride)
        rmw4(hb, x4[g], i4[g]);

    __syncthreads();

    // block reduction: 224 copies -> 1 (sum, count) per bin.
    // lane-rotated reads keep the 32 loads per (bin, warp) conflict-free.
    for (int bin = tid; bin < NUM_BINS; bin += NTHREADS) {
        float s = 0.0f;
        float c = 0.0f;
        #pragma unroll
        for (int w = 0; w < NWARPS; w++) {
            const float* base = smem + w * HIST_F32_PER_WARP + (bin << 5);
            #pragma unroll
            for (int k = 0; k < 32; k++) {
                int l = (bin + k) & 31;
                float e = base[l];
                float cc = rintf(e * INV_BIAS);   // recover count
                s += e - cc * BIAS;               // recover sum(x)
                c += cc;
            }
        }
        g_psum[blockIdx.x * NUM_BINS + bin] = s;
        g_pcnt[blockIdx.x * NUM_BINS + bin] = c;
    }
}

__global__ void finalize_kernel(const float* __restrict__ target_mean,
                                float* __restrict__ out)
{
    __shared__ float red[NUM_BINS];
    const int b = threadIdx.x;   // 256 threads, one per bin

    float s = 0.0f, c = 0.0f;
    #pragma unroll 4
    for (int blk = 0; blk < GRID; blk++) {
        s += g_psum[blk * NUM_BINS + b];
        c += g_pcnt[blk * NUM_BINS + b];
    }
    float mean = s / fmaxf(c, 1.0f);     // empty segment -> 0 (s == 0)
    float dev  = mean - target_mean[b];
    red[b] = dev * dev;
    __syncthreads();

    #pragma unroll
    for (int off = NUM_BINS / 2; off > 0; off >>= 1) {
        if (b < off) red[b] += red[b + off];
        __syncthreads();
    }
    if (b == 0)
        out[0] = red[0] * (0.01f / (float)NUM_BINS);
}

extern "C" void kernel_launch(void* const* d_in, const int* in_sizes, int n_in,
                              void* d_out, int out_size)
{
    const float* x   = (const float*)d_in[0];
    const int*   idx = (const int*)d_in[1];
    const float* tm  = (const float*)d_in[2];
    float*       out = (float*)d_out;
    const int E = in_sizes[0];

    cudaFuncSetAttribute(seg_hist_kernel,
                         cudaFuncAttributeMaxDynamicSharedMemorySize,
                         SMEM_BYTES);

    seg_hist_kernel<<<GRID, NTHREADS, SMEM_BYTES>>>(x, idx, E);
    finalize_kernel<<<1, NUM_BINS>>>(tm, out);
}

// round 3
// speedup vs baseline: 1.4483x; 1.4483x over previous
#include <cuda_runtime.h>
#include <stdint.h>

#define NUM_BINS   256
#define GRID       152              // GB300: 152 SMs, 1 resident block each
#define NWARPS     7
#define NTHREADS   (NWARPS * 32)    // 224
#define HIST_F32_PER_WARP (NUM_BINS * 32)           // 8192 floats = 32 KB
#define SMEM_FLOATS (NWARPS * HIST_F32_PER_WARP)    // 57344
#define SMEM_BYTES  (SMEM_FLOATS * 4)               // 229376 bytes

#define BIAS 1024.0f
#define INV_BIAS (1.0f / 1024.0f)

// per-block partial results + completion ticket (no cudaMalloc allowed)
__device__ float g_psum[GRID * NUM_BINS];
__device__ float g_pcnt[GRID * NUM_BINS];
__device__ int   g_ticket = 0;

// 4-way wave: exact dedup in registers, then 4 batched LDS + <=4 predicated STS.
// All loads precede all stores -> compiler keeps them batched (4x chain ILP).
__device__ __forceinline__ void rmw4d(float* hb, float4 xv, int4 iv) {
    int b0 = iv.x & 255, b1 = iv.y & 255, b2 = iv.z & 255, b3 = iv.w & 255;
    float v0 = xv.x + BIAS, v1 = xv.y + BIAS, v2 = xv.z + BIAS, v3 = xv.w + BIAS;

    bool l1 = (b1 != b0);
    if (!l1) v0 += v1;

    bool e20 = (b2 == b0);
    bool e21 = (b2 == b1) && l1;
    bool l2  = !(e20 || e21);
    if (e20) v0 += v2;
    if (e21) v1 += v2;

    bool e30 = (b3 == b0);
    bool e31 = (b3 == b1) && l1;
    bool e32 = (b3 == b2) && l2;
    bool l3  = !(e30 || e31 || e32);
    if (e30) v0 += v3;
    if (e31) v1 += v3;
    if (e32) v2 += v3;

    float* p0 = hb + (b0 << 5);
    float* p1 = hb + (b1 << 5);
    float* p2 = hb + (b2 << 5);
    float* p3 = hb + (b3 << 5);
    float e0 = *p0;
    float f1 = *p1;
    float f2 = *p2;
    float f3 = *p3;
    *p0 = e0 + v0;
    if (l1) *p1 = f1 + v1;
    if (l2) *p2 = f2 + v2;
    if (l3) *p3 = f3 + v3;
}

__global__ __launch_bounds__(NTHREADS, 1)
void seg_hist_kernel(const float* __restrict__ x,
                     const int*   __restrict__ idx,
                     const float* __restrict__ target_mean,
                     float* __restrict__ out,
                     int E)
{
    extern __shared__ float smem[];
    const int tid  = threadIdx.x;
    const int lane = tid & 31;
    const int warp = tid >> 5;

    float* hb = smem + warp * HIST_F32_PER_WARP + lane;

    // zero the private histograms (vectorized)
    float4* sz = (float4*)smem;
    #pragma unroll 4
    for (int i = tid; i < SMEM_FLOATS / 4; i += NTHREADS)
        sz[i] = make_float4(0.f, 0.f, 0.f, 0.f);
    __syncthreads();

    const float4* __restrict__ x4 = (const float4*)x;
    const int4*   __restrict__ i4 = (const int4*)idx;
    const int G = E >> 2;                       // float4 groups
    const int stride = GRID * NTHREADS;

    int g = blockIdx.x * NTHREADS + tid;

    // main loop: 4 groups (16 elements) per iteration, streaming loads
    for (; g + 3 * stride < G; g += 4 * stride) {
        float4 a0 = __ldcs(&x4[g]);
        float4 a1 = __ldcs(&x4[g + stride]);
        float4 a2 = __ldcs(&x4[g + 2 * stride]);
        float4 a3 = __ldcs(&x4[g + 3 * stride]);
        int4   b0 = __ldcs(&i4[g]);
        int4   b1 = __ldcs(&i4[g + stride]);
        int4   b2 = __ldcs(&i4[g + 2 * stride]);
        int4   b3 = __ldcs(&i4[g + 3 * stride]);
        rmw4d(hb, a0, b0);
        rmw4d(hb, a1, b1);
        rmw4d(hb, a2, b2);
        rmw4d(hb, a3, b3);
    }
    for (; g < G; g += stride)
        rmw4d(hb, __ldcs(&x4[g]), __ldcs(&i4[g]));

    // sub-float4 remainder (E not multiple of 4): block 0, warp 0
    int rem = E & 3;
    if (rem && blockIdx.x == 0 && warp == 0 && lane < rem) {
        int e = (E & ~3) + lane;
        float v = x[e] + BIAS;
        float* p = hb + ((idx[e] & 255) << 5);
        *p = *p + v;
    }
    __syncthreads();

    // block reduction: 224 lane-columns -> 1 (sum, count) per bin
    for (int bin = tid; bin < NUM_BINS; bin += NTHREADS) {
        float s = 0.0f, c = 0.0f;
        #pragma unroll
        for (int w = 0; w < NWARPS; w++) {
            const float* base = smem + w * HIST_F32_PER_WARP + (bin << 5);
            #pragma unroll
            for (int k = 0; k < 32; k++) {
                int l = (bin + k) & 31;          // rotated, conflict-free
                float e = base[l];
                float cc = rintf(e * INV_BIAS);  // recover count
                s += e - cc * BIAS;              // recover sum(x)
                c += cc;
            }
        }
        g_psum[blockIdx.x * NUM_BINS + bin] = s;
        g_pcnt[blockIdx.x * NUM_BINS + bin] = c;
    }
    __syncthreads();
    __threadfence();

    // last block finishes the reduction
    __shared__ int s_last;
    if (tid == 0)
        s_last = (atomicAdd(&g_ticket, 1) == GRID - 1) ? 1 : 0;
    __syncthreads();
    if (!s_last) return;

    // warp w sums blocks {w, w+7, ...} for all 256 bins (coalesced, L2-hot)
    float accS[8], accC[8];
    #pragma unroll
    for (int j = 0; j < 8; j++) { accS[j] = 0.f; accC[j] = 0.f; }
    for (int blk = warp; blk < GRID; blk += NWARPS) {
        #pragma unroll
        for (int j = 0; j < 8; j++) {
            int bin = lane + j * 32;
            accS[j] += g_psum[blk * NUM_BINS + bin];
            accC[j] += g_pcnt[blk * NUM_BINS + bin];
        }
    }
    float* sS  = smem;                     // [7][256]
    float* sC  = smem + NWARPS * NUM_BINS; // [7][256]
    float* red = smem + 2 * NWARPS * NUM_BINS;
    #pragma unroll
    for (int j = 0; j < 8; j++) {
        sS[warp * NUM_BINS + lane + j * 32] = accS[j];
        sC[warp * NUM_BINS + lane + j * 32] = accC[j];
    }
    __syncthreads();

    for (int bin = tid; bin < NUM_BINS; bin += NTHREADS) {
        float s = 0.f, c = 0.f;
        #pragma unroll
        for (int w = 0; w < NWARPS; w++) {
            s += sS[w * NUM_BINS + bin];
            c += sC[w * NUM_BINS + bin];
        }
        float mean = s / fmaxf(c, 1.0f);   // empty segment -> 0
        float dv   = mean - target_mean[bin];
        red[bin]   = dv * dv;
    }
    __syncthreads();

    #pragma unroll
    for (int off = NUM_BINS / 2; off > 0; off >>= 1) {
        if (tid < off) red[tid] += red[tid + off];
        __syncthreads();
    }
    if (tid == 0) {
        out[0] = red[0] * (0.01f / (float)NUM_BINS);
        g_ticket = 0;                      // reset for next graph replay
    }
}

extern "C" void kernel_launch(void* const* d_in, const int* in_sizes, int n_in,
                              void* d_out, int out_size)
{
    const float* x   = (const float*)d_in[0];
    const int*   idx = (const int*)d_in[1];
    const float* tm  = (const float*)d_in[2];
    float*       out = (float*)d_out;
    const int E = in_sizes[0];

    cudaFuncSetAttribute(seg_hist_kernel,
                         cudaFuncAttributeMaxDynamicSharedMemorySize,
                         SMEM_BYTES);

    seg_hist_kernel<<<GRID, NTHREADS, SMEM_BYTES>>>(x, idx, tm, out, E);
}

// round 4
// speedup vs baseline: 1.6338x; 1.1281x over previous
#include <cuda_runtime.h>
#include <stdint.h>

#define NUM_BINS   256
#define GRID       152              // GB300: 152 SMs, 1 resident block each
#define NWARPS     7
#define NTHREADS   (NWARPS * 32)    // 224
#define HIST_F32_PER_WARP (NUM_BINS * 32)           // 8192 floats = 32 KB
#define SMEM_FLOATS (NWARPS * HIST_F32_PER_WARP)    // 57344
#define SMEM_BYTES  (SMEM_FLOATS * 4)               // 229376 bytes

#define BIAS 1024.0f
#define INV_BIAS (1.0f / 1024.0f)
#define BATCH 8                      // float4-groups per pipeline stage (16 LDG.128)

// per-block partial results + completion ticket (no cudaMalloc allowed)
__device__ float g_psum[GRID * NUM_BINS];
__device__ float g_pcnt[GRID * NUM_BINS];
__device__ int   g_ticket = 0;

// 4-way wave: exact dedup in registers, then 4 batched LDS + <=4 predicated STS.
__device__ __forceinline__ void rmw4d(float* hb, float4 xv, int4 iv) {
    int b0 = iv.x & 255, b1 = iv.y & 255, b2 = iv.z & 255, b3 = iv.w & 255;
    float v0 = xv.x + BIAS, v1 = xv.y + BIAS, v2 = xv.z + BIAS, v3 = xv.w + BIAS;

    bool l1 = (b1 != b0);
    if (!l1) v0 += v1;

    bool e20 = (b2 == b0);
    bool e21 = (b2 == b1) && l1;
    bool l2  = !(e20 || e21);
    if (e20) v0 += v2;
    if (e21) v1 += v2;

    bool e30 = (b3 == b0);
    bool e31 = (b3 == b1) && l1;
    bool e32 = (b3 == b2) && l2;
    bool l3  = !(e30 || e31 || e32);
    if (e30) v0 += v3;
    if (e31) v1 += v3;
    if (e32) v2 += v3;

    float* p0 = hb + (b0 << 5);
    float* p1 = hb + (b1 << 5);
    float* p2 = hb + (b2 << 5);
    float* p3 = hb + (b3 << 5);
    float e0 = *p0;
    float f1 = *p1;
    float f2 = *p2;
    float f3 = *p3;
    *p0 = e0 + v0;
    if (l1) *p1 = f1 + v1;
    if (l2) *p2 = f2 + v2;
    if (l3) *p3 = f3 + v3;
}

__global__ __launch_bounds__(NTHREADS, 1)
void seg_hist_kernel(const float* __restrict__ x,
                     const int*   __restrict__ idx,
                     const float* __restrict__ target_mean,
                     float* __restrict__ out,
                     int E)
{
    extern __shared__ float smem[];
    const int tid  = threadIdx.x;
    const int lane = tid & 31;
    const int warp = tid >> 5;

    float* hb = smem + warp * HIST_F32_PER_WARP + lane;

    // zero the private histograms (vectorized)
    float4* sz = (float4*)smem;
    #pragma unroll 4
    for (int i = tid; i < SMEM_FLOATS / 4; i += NTHREADS)
        sz[i] = make_float4(0.f, 0.f, 0.f, 0.f);
    __syncthreads();

    const float4* __restrict__ x4 = (const float4*)x;
    const int4*   __restrict__ i4 = (const int4*)idx;
    const int G = E >> 2;                       // float4 groups
    const int stride = GRID * NTHREADS;
    const int step = BATCH * stride;

    int g = blockIdx.x * NTHREADS + tid;

    // software-pipelined main loop: consume batch i while batch i+1's
    // 16 LDG.128 are in flight -> ~14 KB/SM sustained in-flight bytes.
    if (g + (BATCH - 1) * stride < G) {
        float4 a[BATCH]; int4 b[BATCH];
        #pragma unroll
        for (int j = 0; j < BATCH; j++) {
            a[j] = __ldcs(&x4[g + j * stride]);
            b[j] = __ldcs(&i4[g + j * stride]);
        }
        int gn = g + step;
        while (gn + (BATCH - 1) * stride < G) {
            float4 na[BATCH]; int4 nb[BATCH];
            #pragma unroll
            for (int j = 0; j < BATCH; j++) {
                na[j] = __ldcs(&x4[gn + j * stride]);
                nb[j] = __ldcs(&i4[gn + j * stride]);
            }
            #pragma unroll
            for (int j = 0; j < BATCH; j++)
                rmw4d(hb, a[j], b[j]);
            #pragma unroll
            for (int j = 0; j < BATCH; j++) { a[j] = na[j]; b[j] = nb[j]; }
            gn += step;
        }
        #pragma unroll
        for (int j = 0; j < BATCH; j++)
            rmw4d(hb, a[j], b[j]);
        g = gn;
    }
    // tail: single groups
    for (; g < G; g += stride)
        rmw4d(hb, __ldcs(&x4[g]), __ldcs(&i4[g]));

    // sub-float4 remainder: block 0, warp 0
    int rem = E & 3;
    if (rem && blockIdx.x == 0 && warp == 0 && lane < rem) {
        int e = (E & ~3) + lane;
        float v = x[e] + BIAS;
        float* p = hb + ((idx[e] & 255) << 5);
        *p = *p + v;
    }
    __syncthreads();

    // block reduction: 224 lane-columns -> 1 (sum, count) per bin
    for (int bin = tid; bin < NUM_BINS; bin += NTHREADS) {
        float s = 0.0f, c = 0.0f;
        #pragma unroll
        for (int w = 0; w < NWARPS; w++) {
            const float* base = smem + w * HIST_F32_PER_WARP + (bin << 5);
            #pragma unroll
            for (int k = 0; k < 32; k++) {
                int l = (bin + k) & 31;          // rotated, conflict-free
                float e = base[l];
                float cc = rintf(e * INV_BIAS);  // recover count
                s += e - cc * BIAS;              // recover sum(x)
                c += cc;
            }
        }
        g_psum[blockIdx.x * NUM_BINS + bin] = s;
        g_pcnt[blockIdx.x * NUM_BINS + bin] = c;
    }
    __syncthreads();
    __threadfence();

    // last block finishes the reduction
    __shared__ int s_last;
    if (tid == 0)
        s_last = (atomicAdd(&g_ticket, 1) == GRID - 1) ? 1 : 0;
    __syncthreads();
    if (!s_last) return;

    // warp w sums blocks {w, w+7, ...} for all 256 bins (coalesced, L2-hot)
    float accS[8], accC[8];
    #pragma unroll
    for (int j = 0; j < 8; j++) { accS[j] = 0.f; accC[j] = 0.f; }
    for (int blk = warp; blk < GRID; blk += NWARPS) {
        #pragma unroll
        for (int j = 0; j < 8; j++) {
            int bin = lane + j * 32;
            accS[j] += g_psum[blk * NUM_BINS + bin];
            accC[j] += g_pcnt[blk * NUM_BINS + bin];
        }
    }
    float* sS  = smem;                     // [7][256]
    float* sC  = smem + NWARPS * NUM_BINS; // [7][256]
    float* red = smem + 2 * NWARPS * NUM_BINS;
    #pragma unroll
    for (int j = 0; j < 8; j++) {
        sS[warp * NUM_BINS + lane + j * 32] = accS[j];
        sC[warp * NUM_BINS + lane + j * 32] = accC[j];
    }
    __syncthreads();

    for (int bin = tid; bin < NUM_BINS; bin += NTHREADS) {
        float s = 0.f, c = 0.f;
        #pragma unroll
        for (int w = 0; w < NWARPS; w++) {
            s += sS[w * NUM_BINS + bin];
            c += sC[w * NUM_BINS + bin];
        }
        float mean = s / fmaxf(c, 1.0f);   // empty segment -> 0
        float dv   = mean - target_mean[bin];
        red[bin]   = dv * dv;
    }
    __syncthreads();

    #pragma unroll
    for (int off = NUM_BINS / 2; off > 0; off >>= 1) {
        if (tid < off) red[tid] += red[tid + off];
        __syncthreads();
    }
    if (tid == 0) {
        out[0] = red[0] * (0.01f / (float)NUM_BINS);
        g_ticket = 0;                      // reset for next graph replay
    }
}

extern "C" void kernel_launch(void* const* d_in, const int* in_sizes, int n_in,
                              void* d_out, int out_size)
{
    const float* x   = (const float*)d_in[0];
    const int*   idx = (const int*)d_in[1];
    const float* tm  = (const float*)d_in[2];
    float*       out = (float*)d_out;
    const int E = in_sizes[0];

    cudaFuncSetAttribute(seg_hist_kernel,
                         cudaFuncAttributeMaxDynamicSharedMemorySize,
                         SMEM_BYTES);

    seg_hist_kernel<<<GRID, NTHREADS, SMEM_BYTES>>>(x, idx, tm, out, E);
}